// round 11
// baseline (speedup 1.0000x reference)
#include <cuda_runtime.h>

#define BDIM 512
#define LL   2048
#define CC   12
#define NDIL 8
#define KK   8
#define GG   32
#define NCP  6

#define SCAT_OFF (2 * CC * LL)                 // 49152 floats
#define SMEM_FLOATS (SCAT_OFF + 16 * 256)      // 53248 floats = 212992 B

typedef unsigned long long u64;
typedef unsigned int u32;

__device__ __forceinline__ int swz(int x){ return x ^ (((x>>5)^(x>>10))&31); }

__device__ __forceinline__ u64 pack2(float lo, float hi){
  u64 r; asm("mov.b64 %0, {%1,%2};" : "=l"(r) : "f"(lo), "f"(hi)); return r;
}
__device__ __forceinline__ u64 dup2(float v){
  u64 r; asm("mov.b64 %0, {%1,%1};" : "=l"(r) : "f"(v)); return r;
}
__device__ __forceinline__ void unpack2(u64 v, float& lo, float& hi){
  asm("mov.b64 {%0,%1}, %2;" : "=f"(lo), "=f"(hi) : "l"(v));
}
__device__ __forceinline__ u64 ffma2(u64 a, u64 b, u64 c){
  u64 r; asm("fma.rn.f32x2 %0, %1, %2, %3;" : "=l"(r) : "l"(a), "l"(b), "l"(c)); return r;
}
__device__ __forceinline__ u64 fmul2(u64 a, u64 b){
  u64 r; asm("mul.rn.f32x2 %0, %1, %2;" : "=l"(r) : "l"(a), "l"(b)); return r;
}
// embed k into low 3 mantissa bits: one LOP3 (R8-proven)
__device__ __forceinline__ float embed(float v, int k){
  u32 b = (__float_as_uint(v) & ~7u) | (u32)k;
  return __uint_as_float(b);
}

// one summed tap; jt valid iff 0 <= jt < P (else 0; wrapped addr harmless)
template<int DI>
__device__ __forceinline__ float tap(const float* __restrict__ sm, const int ro[6],
                                     int phase, int jt){
  constexpr int d = 1 << DI;
  constexpr int P = LL >> DI;
  int x = (phase + jt * d) & (LL - 1);
  int a = swz(x);
  float s = (sm[ro[0]+a] + sm[ro[1]+a]) + (sm[ro[2]+a] + sm[ro[3]+a])
          + (sm[ro[4]+a] + sm[ro[5]+a]);
  return ((unsigned)jt < (unsigned)P) ? s : 0.0f;
}

// two consecutive positions (j in lo halves, j+1 in hi halves) from the pair
// window: 8 packed dots, scalar embed, max/min trees per position.
__device__ __forceinline__ void pair_mm(const u64 wd[72], const u64 P9[9], int rot,
                                        float& Ma, float& Na, float& Mb, float& Nb){
  u64 acc[8];
  u64 t0 = P9[rot % 9];
  #pragma unroll
  for (int k = 0; k < 8; ++k) acc[k] = fmul2(wd[k * 9], t0);
  #pragma unroll
  for (int t = 1; t < 9; ++t){
    u64 wt = P9[(rot + t) % 9];
    #pragma unroll
    for (int k = 0; k < 8; ++k) acc[k] = ffma2(wd[k * 9 + t], wt, acc[k]);
  }
  float ea[8], eb[8];
  #pragma unroll
  for (int k = 0; k < 8; ++k){
    float va, vb;
    unpack2(acc[k], va, vb);
    ea[k] = embed(va, k);
    eb[k] = embed(vb, k);
  }
  Ma = fmaxf(fmaxf(fmaxf(ea[0],ea[1]), fmaxf(ea[2],ea[3])),
             fmaxf(fmaxf(ea[4],ea[5]), fmaxf(ea[6],ea[7])));
  Na = fminf(fminf(fminf(ea[0],ea[1]), fminf(ea[2],ea[3])),
             fminf(fminf(ea[4],ea[5]), fminf(ea[6],ea[7])));
  Mb = fmaxf(fmaxf(fmaxf(eb[0],eb[1]), fmaxf(eb[2],eb[3])),
             fmaxf(fmaxf(eb[4],eb[5]), fmaxf(eb[6],eb[7])));
  Nb = fminf(fminf(fminf(eb[0],eb[1]), fminf(eb[2],eb[3])),
             fminf(fminf(eb[4],eb[5]), fminf(eb[6],eb[7])));
}

template<int DI>
__device__ __forceinline__ void run_di(const float* __restrict__ sm,
                                       float* __restrict__ scm,
                                       const float* __restrict__ W,
                                       const int*   __restrict__ I,
                                       float* __restrict__ out,
                                       int b, int warp, int lane)
{
  constexpr int d     = 1 << DI;
  constexpr int P     = LL >> DI;
  constexpr int logP  = 11 - DI;
  constexpr int SEG   = (P < 64) ? P : 64;    // {64,...,64,32,16}
  constexpr int NSEG  = 64 / SEG;
  constexpr int NPAIR = SEG / 2;              // pairs per segment
  constexpr int NPB   = NPAIR / 9;            // full 9-pair blocks
  constexpr int PREM  = NPAIR - 9 * NPB;      // 64:3+5, 32:1+7, 16:0+8

  for (int it = 0; it < 4; ++it){
    const int task = warp * 4 + it;
    const int diff = task >> 5, g = task & 31;

    const int* Ip = I + ((DI * 2 + diff) * GG + g) * NCP;
    int ro[6];
    #pragma unroll
    for (int j = 0; j < NCP; ++j) ro[j] = diff * CC * LL + __ldg(Ip + j) * LL;

    // dup-packed weights: wd[k*9+t] = (w[k][t], w[k][t])
    const float* Wp = W + (size_t)((DI * 2 + diff) * (KK * GG) + g * KK) * 9;
    u64 wd[72 / 2 * 2];   // 36 u64
    #pragma unroll
    for (int k = 0; k < 8; ++k)
      #pragma unroll
      for (int t = 0; t < 9; ++t)
        wd[k * 9 + t] = dup2(__ldg(Wp + k * 9 + t));

    // zero this warp's private max columns (lane-private, no sync)
    #pragma unroll
    for (int k = 0; k < KK; ++k) scm[k << 5] = 0.0f;
    u64 cnt = 0ull;   // 8x8-bit min-count fields (<=64 per field per task)

    #pragma unroll 1
    for (int sg = 0; sg < NSEG; ++sg){
      const int q     = lane * 64 + sg * SEG;
      const int phase = q >> logP;
      const int j0    = q & (P - 1);

      // init pair window: P9[r] = (s[j0-4+r], s[j0-3+r]); carry = s[j0+5]
      float s0[10];
      #pragma unroll
      for (int r = 0; r < 10; ++r) s0[r] = tap<DI>(sm, ro, phase, j0 - 4 + r);
      u64 P9[9];
      #pragma unroll
      for (int r = 0; r < 9; ++r) P9[r] = pack2(s0[r], s0[r + 1]);
      float carry = s0[9];

      int jc = 0;
      #pragma unroll 1
      for (int blk = 0; blk < NPB; ++blk){
        #pragma unroll
        for (int u = 0; u < 9; ++u){
          const int jlo = j0 + jc + 2 * u;
          float nt1 = tap<DI>(sm, ro, phase, jlo + 6);
          float nt2 = tap<DI>(sm, ro, phase, jlo + 7);
          float Ma, Na, Mb, Nb;
          pair_mm(wd, P9, (2 * u) % 9, Ma, Na, Mb, Nb);
          scm[(__float_as_uint(Ma) & 7u) << 5] += Ma;
          scm[(__float_as_uint(Mb) & 7u) << 5] += Mb;
          cnt += 1ull << ((__float_as_uint(Na) & 7u) << 3);
          cnt += 1ull << ((__float_as_uint(Nb) & 7u) << 3);
          P9[(2 * u) % 9]     = pack2(carry, nt1);
          P9[(2 * u + 1) % 9] = pack2(nt1, nt2);
          carry = nt2;
        }
        jc += 18;
      }
      #pragma unroll
      for (int u = 0; u < PREM; ++u){
        const int jlo = j0 + jc + 2 * u;
        float nt1 = tap<DI>(sm, ro, phase, jlo + 6);
        float nt2 = tap<DI>(sm, ro, phase, jlo + 7);
        float Ma, Na, Mb, Nb;
        pair_mm(wd, P9, (2 * u) % 9, Ma, Na, Mb, Nb);
        scm[(__float_as_uint(Ma) & 7u) << 5] += Ma;
        scm[(__float_as_uint(Mb) & 7u) << 5] += Mb;
        cnt += 1ull << ((__float_as_uint(Na) & 7u) << 3);
        cnt += 1ull << ((__float_as_uint(Nb) & 7u) << 3);
        P9[(2 * u) % 9]     = pack2(carry, nt1);
        P9[(2 * u + 1) % 9] = pack2(nt1, nt2);
        carry = nt2;
      }
    }

    // diff stream Lout = 2047: subtract phantom output position l = 2047.
    // It is the hi half of lane 31's final pair (phase d-1, j = P-1); the dup
    // recompute is lane-wise IEEE-identical -> exact cancel.
    if (diff && lane == 31){
      u64 w9[9];
      #pragma unroll
      for (int t = 0; t < 9; ++t)
        w9[t] = dup2(tap<DI>(sm, ro, d - 1, P - 1 - 4 + t));
      float Ma, Na, Mb, Nb;
      pair_mm(wd, w9, 0, Ma, Na, Mb, Nb);
      scm[(__float_as_uint(Ma) & 7u) << 5] -= Ma;
      cnt -= 1ull << ((__float_as_uint(Na) & 7u) << 3);
    }

    // cross-lane reduction + write
    float* o = out + (size_t)b * (NDIL * 2 * 2 * GG * KK)
                   + ((DI * 2 + diff) * 2) * (GG * KK) + g * KK;
    #pragma unroll
    for (int k = 0; k < KK; ++k){
      float vm = scm[k << 5];
      float vn = (float)((cnt >> (k << 3)) & 0xffull);
      #pragma unroll
      for (int off = 16; off > 0; off >>= 1){
        vm += __shfl_xor_sync(0xffffffffu, vm, off);
        vn += __shfl_xor_sync(0xffffffffu, vn, off);
      }
      if (lane == 0){
        o[k]           = vm;
        o[GG * KK + k] = vn;
      }
    }
  }
}

__global__ __launch_bounds__(BDIM, 1)
void hydra_kernel(const float* __restrict__ X,
                  const float* __restrict__ W,
                  const int*   __restrict__ I,
                  float* __restrict__ out)
{
  extern __shared__ float sm[];  // X (swz) | diff (diff[2047]=0) | per-warp max columns

  const int di = blockIdx.x;
  const int b  = blockIdx.y;
  const int tid = threadIdx.x;

  const float* Xb = X + (size_t)b * CC * LL;

  for (int i = tid; i < CC * LL; i += BDIM){
    int l = i & (LL - 1);
    float v  = Xb[i];
    float nv = (l < LL - 1) ? Xb[i + 1] : v;
    int a = swz(l);
    int c = i >> 11;
    sm[c * LL + a]           = v;
    sm[CC * LL + c * LL + a] = nv - v;
  }
  __syncthreads();

  const int warp = tid >> 5, lane = tid & 31;
  float* scm = sm + SCAT_OFF + warp * 256 + lane;

  switch (di){
    case 0: run_di<0>(sm, scm, W, I, out, b, warp, lane); break;
    case 1: run_di<1>(sm, scm, W, I, out, b, warp, lane); break;
    case 2: run_di<2>(sm, scm, W, I, out, b, warp, lane); break;
    case 3: run_di<3>(sm, scm, W, I, out, b, warp, lane); break;
    case 4: run_di<4>(sm, scm, W, I, out, b, warp, lane); break;
    case 5: run_di<5>(sm, scm, W, I, out, b, warp, lane); break;
    case 6: run_di<6>(sm, scm, W, I, out, b, warp, lane); break;
    default: run_di<7>(sm, scm, W, I, out, b, warp, lane); break;
  }
}

extern "C" void kernel_launch(void* const* d_in, const int* in_sizes, int n_in,
                              void* d_out, int out_size)
{
  const float* X   = (const float*)d_in[0];   // [B, 12, 2048] f32
  const float* W   = (const float*)d_in[1];   // [8, 2, 256, 1, 9] f32
  const int*   I   = (const int*)  d_in[2];   // [8, 2, 32, 6] i32
  float*       out = (float*)d_out;           // [B, 8192] f32

  const int B = in_sizes[0] / (CC * LL);
  const size_t smem = (size_t)SMEM_FLOATS * sizeof(float);   // 212992 B

  cudaFuncSetAttribute(hydra_kernel,
                       cudaFuncAttributeMaxDynamicSharedMemorySize, (int)smem);

  dim3 grid(NDIL, B);
  hydra_kernel<<<grid, BDIM, smem>>>(X, W, I, out);
}